// round 15
// baseline (speedup 1.0000x reference)
#include <cuda_runtime.h>
#include <math.h>

#define ZN 1024
#define NA 14
#define NAA 21
#define NV 4096          // 16^3
#define NTHREADS 256

// out layout: Cb [ZN*4*3] | div [ZN*4096] | frames [ZN*3*3]
#define DIV_OFF   (ZN * 12)
#define FR_OFF    (ZN * 12 + ZN * NV)

typedef unsigned long long u64;

__device__ __forceinline__ u64 pk2(float lo, float hi) {
    u64 r; asm("mov.b64 %0,{%1,%2};" : "=l"(r) : "f"(lo), "f"(hi)); return r;
}
__device__ __forceinline__ void upk2(u64 v, float &lo, float &hi) {
    asm("mov.b64 {%0,%1},%2;" : "=f"(lo), "=f"(hi) : "l"(v));
}
__device__ __forceinline__ u64 add2(u64 a, u64 b) {
    u64 r; asm("add.rn.f32x2 %0,%1,%2;" : "=l"(r) : "l"(a), "l"(b)); return r;
}
__device__ __forceinline__ u64 mul2(u64 a, u64 b) {
    u64 r; asm("mul.rn.f32x2 %0,%1,%2;" : "=l"(r) : "l"(a), "l"(b)); return r;
}
__device__ __forceinline__ u64 fma2_(u64 a, u64 b, u64 c) {
    u64 r; asm("fma.rn.f32x2 %0,%1,%2,%3;" : "=l"(r) : "l"(a), "l"(b), "l"(c)); return r;
}
__device__ __forceinline__ float rsqrt_fast(float x) {
    float r; asm("rsqrt.approx.f32 %0,%1;" : "=f"(r) : "f"(x)); return r;
}

// r pair = 1/(d*clip(d,1)^2) = rsqrt( max(d2,eps) * max(d2,1)^2 )
// scalar per lane; MUFU result packs directly into the S/T FMAs.
__device__ __forceinline__ u64 rfactor2(u64 d2) {
    float x, y;
    upk2(d2, x, y);
    float ax = fmaxf(x, 1e-12f);    // guards d=0 AND tiny-negative cancellation
    float mx = fmaxf(x, 1.0f);
    float ex = ax * (mx * mx);
    float ay = fmaxf(y, 1e-12f);
    float my = fmaxf(y, 1.0f);
    float ey = ay * (my * my);
    return pk2(rsqrt_fast(ex), rsqrt_fast(ey));
}

__global__ __launch_bounds__(NTHREADS, 4) void pp_kernel(
    const float* __restrict__ C,
    const int*   __restrict__ L,
    const float* __restrict__ atom_mask,
    const float* __restrict__ charges,
    float* __restrict__ out)
{
    extern __shared__ float sf[];            // 3 * 4096 floats = 48 KB
    float* sfx = sf;
    float* sfy = sf + NV;
    float* sfz = sf + 2 * NV;
    // per atom, 8 duplicated-lane u64s:
    //  [0]=(-2Cx) [1]=(-2Cy) [2]=(-2Cz) [3]=|C|^2 [4]=pc [5]=-pc*Cx [6]=-pc*Cy [7]=-pc*Cz
    __shared__ alignas(16) u64 satom[NA * 8];
    __shared__ float sfr[9];
    __shared__ float sorig[3];

    const int n   = blockIdx.x;
    const int tid = threadIdx.x;
    const float* Cn = C + n * NA * 3;

    if (tid < NA) {
        int lbl = L[n];
        if (lbl == -1) lbl = NAA - 1;
        float cx = Cn[tid * 3 + 0];
        float cy = Cn[tid * 3 + 1];
        float cz = Cn[tid * 3 + 2];
        float pc = charges[lbl * NA + tid] * atom_mask[n * NA + tid];
        float c2 = cx * cx + cy * cy + cz * cz;
        satom[tid * 8 + 0] = pk2(-2.0f * cx, -2.0f * cx);
        satom[tid * 8 + 1] = pk2(-2.0f * cy, -2.0f * cy);
        satom[tid * 8 + 2] = pk2(-2.0f * cz, -2.0f * cz);
        satom[tid * 8 + 3] = pk2(c2, c2);
        satom[tid * 8 + 4] = pk2(pc, pc);
        satom[tid * 8 + 5] = pk2(-pc * cx, -pc * cx);
        satom[tid * 8 + 6] = pk2(-pc * cy, -pc * cy);
        satom[tid * 8 + 7] = pk2(-pc * cz, -pc * cz);
    }
    if (tid == 0) {
        float Nx = Cn[0], Ny = Cn[1], Nz = Cn[2];
        float Ax = Cn[3], Ay = Cn[4], Az = Cn[5];
        float Bx = Cn[6], By = Cn[7], Bz = Cn[8];   // "C" atom
        float b1x = Ax - Nx, b1y = Ay - Ny, b1z = Az - Nz;
        float b2x = Bx - Ax, b2y = By - Ay, b2z = Bz - Az;
        float b3x = b1y * b2z - b1z * b2y;
        float b3y = b1z * b2x - b1x * b2z;
        float b3z = b1x * b2y - b1y * b2x;
        float cbx = Ax - 0.58273431f * b2x + 0.56802827f * b1x - 0.54067466f * b3x;
        float cby = Ay - 0.58273431f * b2y + 0.56802827f * b1y - 0.54067466f * b3y;
        float cbz = Az - 0.58273431f * b2z + 0.56802827f * b1z - 0.54067466f * b3z;
        float yx = cbx - Ax, yy = cby - Ay, yz = cbz - Az;
        float ynrm = fmaxf(sqrtf(yx * yx + yy * yy + yz * yz), 1e-6f);
        float yux = yx / ynrm, yuy = yy / ynrm, yuz = yz / ynrm;
        float xrx = Bx - Nx, xry = By - Ny, xrz = Bz - Nz;
        float xp  = xrx * yux + xry * yuy + xrz * yuz;
        float xx = xrx - xp, xy = xry - xp, xz = xrz - xp;
        float xnrm = fmaxf(sqrtf(xx * xx + xy * xy + xz * xz), 1e-6f);
        float xux = xx / xnrm, xuy = xy / xnrm, xuz = xz / xnrm;
        float zx = xuy * yuz - xuz * yuy;
        float zy = xuz * yux - xux * yuz;
        float zz = xux * yuy - xuy * yux;
        float znrm = fmaxf(sqrtf(zx * zx + zy * zy + zz * zz), 1e-6f);
        float zux = zx / znrm, zuy = zy / znrm, zuz = zz / znrm;

        sfr[0] = xux; sfr[1] = xuy; sfr[2] = xuz;
        sfr[3] = yux; sfr[4] = yuy; sfr[5] = yuz;
        sfr[6] = zux; sfr[7] = zuy; sfr[8] = zuz;
        sorig[0] = cbx; sorig[1] = cby; sorig[2] = cbz;

        float* cbo = out + n * 12;
        cbo[0] = Nx;  cbo[1] = Ny;  cbo[2] = Nz;
        cbo[3] = Ax;  cbo[4] = Ay;  cbo[5] = Az;
        cbo[6] = Bx;  cbo[7] = By;  cbo[8] = Bz;
        cbo[9] = cbx; cbo[10] = cby; cbo[11] = cbz;
        float* fro = out + FR_OFF + n * 9;
        fro[0] = xux; fro[1] = xuy; fro[2] = xuz;
        fro[3] = yux; fro[4] = yuy; fro[5] = yuz;
        fro[6] = zux; fro[7] = zuy; fro[8] = zuz;
    }
    __syncthreads();

    const float fr0 = sfr[0], fr1 = sfr[1], fr2 = sfr[2];
    const float ox = sorig[0], oy = sorig[1], oz = sorig[2];

    // thread owns the x-line; 4 voxels per k-iter:
    //   pair A lanes = (x=k,   x=k+8)
    //   pair B lanes = (x=k+4, x=k+12), k = 0..3
    // pair-B positions are recomputed from pair A each iteration (saves 6 u64 regs)
    const float vy = (float)(tid >> 4) - 4.0f;
    const float vz = (float)(tid & 15) - 8.0f;
    float px0 = ox + (-8.0f) * fr0 + vy * sfr[3] + vz * sfr[6];
    float py0 = oy + (-8.0f) * fr1 + vy * sfr[4] + vz * sfr[7];
    float pz0 = oz + (-8.0f) * fr2 + vy * sfr[5] + vz * sfr[8];
    u64 pxA = pk2(px0, px0 + 8.0f * fr0);
    u64 pyA = pk2(py0, py0 + 8.0f * fr1);
    u64 pzA = pk2(pz0, pz0 + 8.0f * fr2);
    const u64 sxp = pk2(fr0, fr0);
    const u64 syp = pk2(fr1, fr1);
    const u64 szp = pk2(fr2, fr2);
    const u64 four2 = pk2(4.0f, 4.0f);

    #pragma unroll 1
    for (int k = 0; k < 4; k++) {
        // pair-B positions derived on the fly
        u64 pxB = fma2_(four2, sxp, pxA);
        u64 pyB = fma2_(four2, syp, pyA);
        u64 pzB = fma2_(four2, szp, pzA);
        // |p|^2 per pair (amortized over the atom loop)
        u64 pp2A = fma2_(pxA, pxA, fma2_(pyA, pyA, mul2(pzA, pzA)));
        u64 pp2B = fma2_(pxB, pxB, fma2_(pyB, pyB, mul2(pzB, pzB)));
        u64 SA = 0ULL, TxA = 0ULL, TyA = 0ULL, TzA = 0ULL;
        u64 SB = 0ULL, TxB = 0ULL, TyB = 0ULL, TzB = 0ULL;
        // unroll 1: minimal live load-temps (anti-spill at the 62-reg cap);
        // latency hiding shifts to the 4th CTA's warps
        #pragma unroll 1
        for (int j = 0; j < NA; j++) {
            ulonglong2 t0 = *reinterpret_cast<const ulonglong2*>(satom + j * 8);     // -2Cx, -2Cy
            ulonglong2 t1 = *reinterpret_cast<const ulonglong2*>(satom + j * 8 + 2); // -2Cz, |C|^2
            // d2 = |p|^2 + (p.(-2C) + |C|^2)
            u64 d2A = add2(pp2A, fma2_(pxA, t0.x, fma2_(pyA, t0.y, fma2_(pzA, t1.x, t1.y))));
            u64 d2B = add2(pp2B, fma2_(pxB, t0.x, fma2_(pyB, t0.y, fma2_(pzB, t1.x, t1.y))));
            u64 rA = rfactor2(d2A);
            u64 rB = rfactor2(d2B);
            ulonglong2 t2 = *reinterpret_cast<const ulonglong2*>(satom + j * 8 + 4); // pc, -pcCx
            ulonglong2 t3 = *reinterpret_cast<const ulonglong2*>(satom + j * 8 + 6); // -pcCy, -pcCz
            SA  = fma2_(rA, t2.x, SA);
            TxA = fma2_(rA, t2.y, TxA);
            TyA = fma2_(rA, t3.x, TyA);
            TzA = fma2_(rA, t3.y, TzA);
            SB  = fma2_(rB, t2.x, SB);
            TxB = fma2_(rB, t2.y, TxB);
            TyB = fma2_(rB, t3.x, TyB);
            TzB = fma2_(rB, t3.y, TzB);
        }
        // f = S*p + T  (T accumulated with -pc*C)
        u64 fxA = fma2_(SA, pxA, TxA);
        u64 fyA = fma2_(SA, pyA, TyA);
        u64 fzA = fma2_(SA, pzA, TzA);
        u64 fxB = fma2_(SB, pxB, TxB);
        u64 fyB = fma2_(SB, pyB, TyB);
        u64 fzB = fma2_(SB, pzB, TzB);

        float v0x, v1x, v0y, v1y, v0z, v1z;
        upk2(fxA, v0x, v1x); upk2(fyA, v0y, v1y); upk2(fzA, v0z, v1z);
        {
            float fn0 = fmaxf(fmaf(v0x, v0x, fmaf(v0y, v0y, v0z * v0z)), 1e-38f);
            float fn1 = fmaxf(fmaf(v1x, v1x, fmaf(v1y, v1y, v1z * v1z)), 1e-38f);
            float r0 = rsqrt_fast(fn0), r1 = rsqrt_fast(fn1);
            int i0 = tid + (k << 8), i1 = i0 + 2048;
            sfx[i0] = v0x * r0; sfx[i1] = v1x * r1;
            sfy[i0] = v0y * r0; sfy[i1] = v1y * r1;
            sfz[i0] = v0z * r0; sfz[i1] = v1z * r1;
        }
        upk2(fxB, v0x, v1x); upk2(fyB, v0y, v1y); upk2(fzB, v0z, v1z);
        {
            float fn0 = fmaxf(fmaf(v0x, v0x, fmaf(v0y, v0y, v0z * v0z)), 1e-38f);
            float fn1 = fmaxf(fmaf(v1x, v1x, fmaf(v1y, v1y, v1z * v1z)), 1e-38f);
            float r0 = rsqrt_fast(fn0), r1 = rsqrt_fast(fn1);
            int i0 = tid + (k << 8) + 1024, i1 = i0 + 2048;
            sfx[i0] = v0x * r0; sfx[i1] = v1x * r1;
            sfy[i0] = v0y * r0; sfy[i1] = v1y * r1;
            sfz[i0] = v0z * r0; sfz[i1] = v1z * r1;
        }
        pxA = add2(pxA, sxp);
        pyA = add2(pyA, syp);
        pzA = add2(pzA, szp);
    }
    __syncthreads();

    // ---- divergence (CELL_DIM r = 1), fully unrolled so x-branches are compile-time ----
    float* dvo = out + DIV_OFF + n * NV;
    const int y = tid >> 4;
    const int z = tid & 15;
    #pragma unroll
    for (int k = 0; k < 16; k++) {
        int i = tid + (k << 8);
        float ddx, ddy, ddz;
        if (k == 0)        ddx = sfx[i + 256] - sfx[i];
        else if (k == 15)  ddx = sfx[i] - sfx[i - 256];
        else               ddx = 0.5f * (sfx[i + 256] - sfx[i - 256]);
        if (y == 0)        ddy = sfy[i + 16] - sfy[i];
        else if (y == 15)  ddy = sfy[i] - sfy[i - 16];
        else               ddy = 0.5f * (sfy[i + 16] - sfy[i - 16]);
        if (z == 0)        ddz = sfz[i + 1] - sfz[i];
        else if (z == 15)  ddz = sfz[i] - sfz[i - 1];
        else               ddz = 0.5f * (sfz[i + 1] - sfz[i - 1]);
        dvo[i] = ddx + ddy + ddz;
    }
}

extern "C" void kernel_launch(void* const* d_in, const int* in_sizes, int n_in,
                              void* d_out, int out_size) {
    const float* C         = (const float*)d_in[0];
    const int*   L         = (const int*)d_in[1];
    const float* atom_mask = (const float*)d_in[2];
    const float* charges   = (const float*)d_in[3];
    float* out = (float*)d_out;

    static bool attr_set = false;
    if (!attr_set) {
        cudaFuncSetAttribute(pp_kernel, cudaFuncAttributeMaxDynamicSharedMemorySize, 64 * 1024);
        attr_set = true;
    }
    pp_kernel<<<ZN, NTHREADS, 3 * NV * sizeof(float)>>>(C, L, atom_mask, charges, out);
}

// round 16
// speedup vs baseline: 1.0689x; 1.0689x over previous
#include <cuda_runtime.h>
#include <math.h>

#define ZN 1024
#define NA 14
#define NAA 21
#define NV 4096          // 16^3
#define NTHREADS 256

// out layout: Cb [ZN*4*3] | div [ZN*4096] | frames [ZN*3*3]
#define DIV_OFF   (ZN * 12)
#define FR_OFF    (ZN * 12 + ZN * NV)

typedef unsigned long long u64;

__device__ __forceinline__ u64 pk2(float lo, float hi) {
    u64 r; asm("mov.b64 %0,{%1,%2};" : "=l"(r) : "f"(lo), "f"(hi)); return r;
}
__device__ __forceinline__ void upk2(u64 v, float &lo, float &hi) {
    asm("mov.b64 {%0,%1},%2;" : "=f"(lo), "=f"(hi) : "l"(v));
}
__device__ __forceinline__ u64 add2(u64 a, u64 b) {
    u64 r; asm("add.rn.f32x2 %0,%1,%2;" : "=l"(r) : "l"(a), "l"(b)); return r;
}
__device__ __forceinline__ u64 mul2(u64 a, u64 b) {
    u64 r; asm("mul.rn.f32x2 %0,%1,%2;" : "=l"(r) : "l"(a), "l"(b)); return r;
}
__device__ __forceinline__ u64 fma2_(u64 a, u64 b, u64 c) {
    u64 r; asm("fma.rn.f32x2 %0,%1,%2,%3;" : "=l"(r) : "l"(a), "l"(b), "l"(c)); return r;
}
__device__ __forceinline__ float rsqrt_fast(float x) {
    float r; asm("rsqrt.approx.f32 %0,%1;" : "=f"(r) : "f"(x)); return r;
}

// r pair = 1/(d*clip(d,1)^2) = rsqrt( max(d2,eps) * max(d2,1)^2 )
// scalar per lane; MUFU result packs directly into the S/T FMAs.
__device__ __forceinline__ u64 rfactor2(u64 d2) {
    float x, y;
    upk2(d2, x, y);
    float ax = fmaxf(x, 1e-12f);    // guards d=0 AND tiny-negative cancellation
    float mx = fmaxf(x, 1.0f);
    float ex = ax * (mx * mx);
    float ay = fmaxf(y, 1e-12f);
    float my = fmaxf(y, 1.0f);
    float ey = ay * (my * my);
    return pk2(rsqrt_fast(ex), rsqrt_fast(ey));
}

__global__ __launch_bounds__(NTHREADS, 4) void pp_kernel(
    const float* __restrict__ C,
    const int*   __restrict__ L,
    const float* __restrict__ atom_mask,
    const float* __restrict__ charges,
    float* __restrict__ out)
{
    extern __shared__ float sf[];            // 3 * 4096 floats = 48 KB
    float* sfx = sf;
    float* sfy = sf + NV;
    float* sfz = sf + 2 * NV;
    // per atom, 8 duplicated-lane u64s:
    //  [0]=(-2Cx) [1]=(-2Cy) [2]=(-2Cz) [3]=|C|^2 [4]=pc [5]=-pc*Cx [6]=-pc*Cy [7]=-pc*Cz
    __shared__ alignas(16) u64 satom[NA * 8];
    __shared__ float sfr[9];
    __shared__ float sorig[3];

    const int n   = blockIdx.x;
    const int tid = threadIdx.x;
    const float* Cn = C + n * NA * 3;

    if (tid < NA) {
        int lbl = L[n];
        if (lbl == -1) lbl = NAA - 1;
        float cx = Cn[tid * 3 + 0];
        float cy = Cn[tid * 3 + 1];
        float cz = Cn[tid * 3 + 2];
        float pc = charges[lbl * NA + tid] * atom_mask[n * NA + tid];
        float c2 = cx * cx + cy * cy + cz * cz;
        satom[tid * 8 + 0] = pk2(-2.0f * cx, -2.0f * cx);
        satom[tid * 8 + 1] = pk2(-2.0f * cy, -2.0f * cy);
        satom[tid * 8 + 2] = pk2(-2.0f * cz, -2.0f * cz);
        satom[tid * 8 + 3] = pk2(c2, c2);
        satom[tid * 8 + 4] = pk2(pc, pc);
        satom[tid * 8 + 5] = pk2(-pc * cx, -pc * cx);
        satom[tid * 8 + 6] = pk2(-pc * cy, -pc * cy);
        satom[tid * 8 + 7] = pk2(-pc * cz, -pc * cz);
    }
    if (tid == 0) {
        float Nx = Cn[0], Ny = Cn[1], Nz = Cn[2];
        float Ax = Cn[3], Ay = Cn[4], Az = Cn[5];
        float Bx = Cn[6], By = Cn[7], Bz = Cn[8];   // "C" atom
        float b1x = Ax - Nx, b1y = Ay - Ny, b1z = Az - Nz;
        float b2x = Bx - Ax, b2y = By - Ay, b2z = Bz - Az;
        float b3x = b1y * b2z - b1z * b2y;
        float b3y = b1z * b2x - b1x * b2z;
        float b3z = b1x * b2y - b1y * b2x;
        float cbx = Ax - 0.58273431f * b2x + 0.56802827f * b1x - 0.54067466f * b3x;
        float cby = Ay - 0.58273431f * b2y + 0.56802827f * b1y - 0.54067466f * b3y;
        float cbz = Az - 0.58273431f * b2z + 0.56802827f * b1z - 0.54067466f * b3z;
        float yx = cbx - Ax, yy = cby - Ay, yz = cbz - Az;
        float ynrm = fmaxf(sqrtf(yx * yx + yy * yy + yz * yz), 1e-6f);
        float yux = yx / ynrm, yuy = yy / ynrm, yuz = yz / ynrm;
        float xrx = Bx - Nx, xry = By - Ny, xrz = Bz - Nz;
        float xp  = xrx * yux + xry * yuy + xrz * yuz;
        float xx = xrx - xp, xy = xry - xp, xz = xrz - xp;
        float xnrm = fmaxf(sqrtf(xx * xx + xy * xy + xz * xz), 1e-6f);
        float xux = xx / xnrm, xuy = xy / xnrm, xuz = xz / xnrm;
        float zx = xuy * yuz - xuz * yuy;
        float zy = xuz * yux - xux * yuz;
        float zz = xux * yuy - xuy * yux;
        float znrm = fmaxf(sqrtf(zx * zx + zy * zy + zz * zz), 1e-6f);
        float zux = zx / znrm, zuy = zy / znrm, zuz = zz / znrm;

        sfr[0] = xux; sfr[1] = xuy; sfr[2] = xuz;
        sfr[3] = yux; sfr[4] = yuy; sfr[5] = yuz;
        sfr[6] = zux; sfr[7] = zuy; sfr[8] = zuz;
        sorig[0] = cbx; sorig[1] = cby; sorig[2] = cbz;

        float* cbo = out + n * 12;
        cbo[0] = Nx;  cbo[1] = Ny;  cbo[2] = Nz;
        cbo[3] = Ax;  cbo[4] = Ay;  cbo[5] = Az;
        cbo[6] = Bx;  cbo[7] = By;  cbo[8] = Bz;
        cbo[9] = cbx; cbo[10] = cby; cbo[11] = cbz;
        float* fro = out + FR_OFF + n * 9;
        fro[0] = xux; fro[1] = xuy; fro[2] = xuz;
        fro[3] = yux; fro[4] = yuy; fro[5] = yuz;
        fro[6] = zux; fro[7] = zuy; fro[8] = zuz;
    }
    __syncthreads();

    const float fr0 = sfr[0], fr1 = sfr[1], fr2 = sfr[2];
    const float ox = sorig[0], oy = sorig[1], oz = sorig[2];

    // thread owns the x-line; 4 voxels per k-iter:
    //   pair A lanes = (x=k,   x=k+8)
    //   pair B lanes = (x=k+4, x=k+12), k = 0..3
    // pair-B positions derived from pair A each iteration (saves 6 u64 regs)
    const float vy = (float)(tid >> 4) - 4.0f;
    const float vz = (float)(tid & 15) - 8.0f;
    float px0 = ox + (-8.0f) * fr0 + vy * sfr[3] + vz * sfr[6];
    float py0 = oy + (-8.0f) * fr1 + vy * sfr[4] + vz * sfr[7];
    float pz0 = oz + (-8.0f) * fr2 + vy * sfr[5] + vz * sfr[8];
    u64 pxA = pk2(px0, px0 + 8.0f * fr0);
    u64 pyA = pk2(py0, py0 + 8.0f * fr1);
    u64 pzA = pk2(pz0, pz0 + 8.0f * fr2);
    const u64 sxp = pk2(fr0, fr0);
    const u64 syp = pk2(fr1, fr1);
    const u64 szp = pk2(fr2, fr2);
    const u64 four2 = pk2(4.0f, 4.0f);

    #pragma unroll 1
    for (int k = 0; k < 4; k++) {
        // pair-B positions derived on the fly
        u64 pxB = fma2_(four2, sxp, pxA);
        u64 pyB = fma2_(four2, syp, pyA);
        u64 pzB = fma2_(four2, szp, pzA);
        // |p|^2 per pair (amortized over the atom loop)
        u64 pp2A = fma2_(pxA, pxA, fma2_(pyA, pyA, mul2(pzA, pzA)));
        u64 pp2B = fma2_(pxB, pxB, fma2_(pyB, pyB, mul2(pzB, pzB)));
        u64 SA = 0ULL, TxA = 0ULL, TyA = 0ULL, TzA = 0ULL;
        u64 SB = 0ULL, TxB = 0ULL, TyB = 0ULL, TzB = 0ULL;
        // unroll 2: halves loop-control overhead vs unroll 1 while keeping the
        // live load-temp set small enough for the 64-reg occ-4 cap
        #pragma unroll 2
        for (int j = 0; j < NA; j++) {
            ulonglong2 t0 = *reinterpret_cast<const ulonglong2*>(satom + j * 8);     // -2Cx, -2Cy
            ulonglong2 t1 = *reinterpret_cast<const ulonglong2*>(satom + j * 8 + 2); // -2Cz, |C|^2
            // d2 = |p|^2 + (p.(-2C) + |C|^2)
            u64 d2A = add2(pp2A, fma2_(pxA, t0.x, fma2_(pyA, t0.y, fma2_(pzA, t1.x, t1.y))));
            u64 d2B = add2(pp2B, fma2_(pxB, t0.x, fma2_(pyB, t0.y, fma2_(pzB, t1.x, t1.y))));
            u64 rA = rfactor2(d2A);
            u64 rB = rfactor2(d2B);
            ulonglong2 t2 = *reinterpret_cast<const ulonglong2*>(satom + j * 8 + 4); // pc, -pcCx
            ulonglong2 t3 = *reinterpret_cast<const ulonglong2*>(satom + j * 8 + 6); // -pcCy, -pcCz
            SA  = fma2_(rA, t2.x, SA);
            TxA = fma2_(rA, t2.y, TxA);
            TyA = fma2_(rA, t3.x, TyA);
            TzA = fma2_(rA, t3.y, TzA);
            SB  = fma2_(rB, t2.x, SB);
            TxB = fma2_(rB, t2.y, TxB);
            TyB = fma2_(rB, t3.x, TyB);
            TzB = fma2_(rB, t3.y, TzB);
        }
        // f = S*p + T  (T accumulated with -pc*C)
        u64 fxA = fma2_(SA, pxA, TxA);
        u64 fyA = fma2_(SA, pyA, TyA);
        u64 fzA = fma2_(SA, pzA, TzA);
        u64 fxB = fma2_(SB, pxB, TxB);
        u64 fyB = fma2_(SB, pyB, TyB);
        u64 fzB = fma2_(SB, pzB, TzB);

        float v0x, v1x, v0y, v1y, v0z, v1z;
        upk2(fxA, v0x, v1x); upk2(fyA, v0y, v1y); upk2(fzA, v0z, v1z);
        {
            float fn0 = fmaxf(fmaf(v0x, v0x, fmaf(v0y, v0y, v0z * v0z)), 1e-38f);
            float fn1 = fmaxf(fmaf(v1x, v1x, fmaf(v1y, v1y, v1z * v1z)), 1e-38f);
            float r0 = rsqrt_fast(fn0), r1 = rsqrt_fast(fn1);
            int i0 = tid + (k << 8), i1 = i0 + 2048;
            sfx[i0] = v0x * r0; sfx[i1] = v1x * r1;
            sfy[i0] = v0y * r0; sfy[i1] = v1y * r1;
            sfz[i0] = v0z * r0; sfz[i1] = v1z * r1;
        }
        upk2(fxB, v0x, v1x); upk2(fyB, v0y, v1y); upk2(fzB, v0z, v1z);
        {
            float fn0 = fmaxf(fmaf(v0x, v0x, fmaf(v0y, v0y, v0z * v0z)), 1e-38f);
            float fn1 = fmaxf(fmaf(v1x, v1x, fmaf(v1y, v1y, v1z * v1z)), 1e-38f);
            float r0 = rsqrt_fast(fn0), r1 = rsqrt_fast(fn1);
            int i0 = tid + (k << 8) + 1024, i1 = i0 + 2048;
            sfx[i0] = v0x * r0; sfx[i1] = v1x * r1;
            sfy[i0] = v0y * r0; sfy[i1] = v1y * r1;
            sfz[i0] = v0z * r0; sfz[i1] = v1z * r1;
        }
        pxA = add2(pxA, sxp);
        pyA = add2(pyA, syp);
        pzA = add2(pzA, szp);
    }
    __syncthreads();

    // ---- divergence (CELL_DIM r = 1), fully unrolled so x-branches are compile-time ----
    float* dvo = out + DIV_OFF + n * NV;
    const int y = tid >> 4;
    const int z = tid & 15;
    #pragma unroll
    for (int k = 0; k < 16; k++) {
        int i = tid + (k << 8);
        float ddx, ddy, ddz;
        if (k == 0)        ddx = sfx[i + 256] - sfx[i];
        else if (k == 15)  ddx = sfx[i] - sfx[i - 256];
        else               ddx = 0.5f * (sfx[i + 256] - sfx[i - 256]);
        if (y == 0)        ddy = sfy[i + 16] - sfy[i];
        else if (y == 15)  ddy = sfy[i] - sfy[i - 16];
        else               ddy = 0.5f * (sfy[i + 16] - sfy[i - 16]);
        if (z == 0)        ddz = sfz[i + 1] - sfz[i];
        else if (z == 15)  ddz = sfz[i] - sfz[i - 1];
        else               ddz = 0.5f * (sfz[i + 1] - sfz[i - 1]);
        dvo[i] = ddx + ddy + ddz;
    }
}

extern "C" void kernel_launch(void* const* d_in, const int* in_sizes, int n_in,
                              void* d_out, int out_size) {
    const float* C         = (const float*)d_in[0];
    const int*   L         = (const int*)d_in[1];
    const float* atom_mask = (const float*)d_in[2];
    const float* charges   = (const float*)d_in[3];
    float* out = (float*)d_out;

    static bool attr_set = false;
    if (!attr_set) {
        cudaFuncSetAttribute(pp_kernel, cudaFuncAttributeMaxDynamicSharedMemorySize, 64 * 1024);
        attr_set = true;
    }
    pp_kernel<<<ZN, NTHREADS, 3 * NV * sizeof(float)>>>(C, L, atom_mask, charges, out);
}

// round 17
// speedup vs baseline: 1.1622x; 1.0873x over previous
#include <cuda_runtime.h>
#include <math.h>

#define ZN 1024
#define NA 14
#define NAA 21
#define NV 4096          // 16^3
#define NTHREADS 256

// out layout: Cb [ZN*4*3] | div [ZN*4096] | frames [ZN*3*3]
#define DIV_OFF   (ZN * 12)
#define FR_OFF    (ZN * 12 + ZN * NV)

typedef unsigned long long u64;

__device__ __forceinline__ u64 pk2(float lo, float hi) {
    u64 r; asm("mov.b64 %0,{%1,%2};" : "=l"(r) : "f"(lo), "f"(hi)); return r;
}
__device__ __forceinline__ void upk2(u64 v, float &lo, float &hi) {
    asm("mov.b64 {%0,%1},%2;" : "=f"(lo), "=f"(hi) : "l"(v));
}
__device__ __forceinline__ u64 add2(u64 a, u64 b) {
    u64 r; asm("add.rn.f32x2 %0,%1,%2;" : "=l"(r) : "l"(a), "l"(b)); return r;
}
__device__ __forceinline__ u64 mul2(u64 a, u64 b) {
    u64 r; asm("mul.rn.f32x2 %0,%1,%2;" : "=l"(r) : "l"(a), "l"(b)); return r;
}
__device__ __forceinline__ u64 fma2_(u64 a, u64 b, u64 c) {
    u64 r; asm("fma.rn.f32x2 %0,%1,%2,%3;" : "=l"(r) : "l"(a), "l"(b), "l"(c)); return r;
}
__device__ __forceinline__ float rsqrt_fast(float x) {
    float r; asm("rsqrt.approx.f32 %0,%1;" : "=f"(r) : "f"(x)); return r;
}

// r pair = 1/(d*clip(d,1)^2) = rsqrt( max(d2,eps) * max(d2,1)^2 )
// scalar per lane; MUFU result packs directly into the S/T FMAs.
__device__ __forceinline__ u64 rfactor2(u64 d2) {
    float x, y;
    upk2(d2, x, y);
    float ax = fmaxf(x, 1e-12f);    // guards d=0 AND tiny-negative cancellation
    float mx = fmaxf(x, 1.0f);
    float ex = ax * (mx * mx);
    float ay = fmaxf(y, 1e-12f);
    float my = fmaxf(y, 1.0f);
    float ey = ay * (my * my);
    return pk2(rsqrt_fast(ex), rsqrt_fast(ey));
}

__global__ __launch_bounds__(NTHREADS, 4) void pp_kernel(
    const float* __restrict__ C,
    const int*   __restrict__ L,
    const float* __restrict__ atom_mask,
    const float* __restrict__ charges,
    float* __restrict__ out)
{
    extern __shared__ float sf[];            // 3 * 4096 floats = 48 KB
    float* sfx = sf;
    float* sfy = sf + NV;
    float* sfz = sf + 2 * NV;
    // per atom, 8 duplicated-lane u64s:
    //  [0]=(-2Cx) [1]=(-2Cy) [2]=(-2Cz) [3]=|C|^2 [4]=pc [5]=-pc*Cx [6]=-pc*Cy [7]=-pc*Cz
    __shared__ alignas(16) u64 satom[NA * 8];
    __shared__ float sfr[9];
    __shared__ float sorig[3];

    const int n   = blockIdx.x;
    const int tid = threadIdx.x;
    const float* Cn = C + n * NA * 3;

    if (tid < NA) {
        int lbl = L[n];
        if (lbl == -1) lbl = NAA - 1;
        float cx = Cn[tid * 3 + 0];
        float cy = Cn[tid * 3 + 1];
        float cz = Cn[tid * 3 + 2];
        float pc = charges[lbl * NA + tid] * atom_mask[n * NA + tid];
        float c2 = cx * cx + cy * cy + cz * cz;
        satom[tid * 8 + 0] = pk2(-2.0f * cx, -2.0f * cx);
        satom[tid * 8 + 1] = pk2(-2.0f * cy, -2.0f * cy);
        satom[tid * 8 + 2] = pk2(-2.0f * cz, -2.0f * cz);
        satom[tid * 8 + 3] = pk2(c2, c2);
        satom[tid * 8 + 4] = pk2(pc, pc);
        satom[tid * 8 + 5] = pk2(-pc * cx, -pc * cx);
        satom[tid * 8 + 6] = pk2(-pc * cy, -pc * cy);
        satom[tid * 8 + 7] = pk2(-pc * cz, -pc * cz);
    }
    if (tid == 0) {
        float Nx = Cn[0], Ny = Cn[1], Nz = Cn[2];
        float Ax = Cn[3], Ay = Cn[4], Az = Cn[5];
        float Bx = Cn[6], By = Cn[7], Bz = Cn[8];   // "C" atom
        float b1x = Ax - Nx, b1y = Ay - Ny, b1z = Az - Nz;
        float b2x = Bx - Ax, b2y = By - Ay, b2z = Bz - Az;
        float b3x = b1y * b2z - b1z * b2y;
        float b3y = b1z * b2x - b1x * b2z;
        float b3z = b1x * b2y - b1y * b2x;
        float cbx = Ax - 0.58273431f * b2x + 0.56802827f * b1x - 0.54067466f * b3x;
        float cby = Ay - 0.58273431f * b2y + 0.56802827f * b1y - 0.54067466f * b3y;
        float cbz = Az - 0.58273431f * b2z + 0.56802827f * b1z - 0.54067466f * b3z;
        float yx = cbx - Ax, yy = cby - Ay, yz = cbz - Az;
        float ynrm = fmaxf(sqrtf(yx * yx + yy * yy + yz * yz), 1e-6f);
        float yux = yx / ynrm, yuy = yy / ynrm, yuz = yz / ynrm;
        float xrx = Bx - Nx, xry = By - Ny, xrz = Bz - Nz;
        float xp  = xrx * yux + xry * yuy + xrz * yuz;
        float xx = xrx - xp, xy = xry - xp, xz = xrz - xp;
        float xnrm = fmaxf(sqrtf(xx * xx + xy * xy + xz * xz), 1e-6f);
        float xux = xx / xnrm, xuy = xy / xnrm, xuz = xz / xnrm;
        float zx = xuy * yuz - xuz * yuy;
        float zy = xuz * yux - xux * yuz;
        float zz = xux * yuy - xuy * yux;
        float znrm = fmaxf(sqrtf(zx * zx + zy * zy + zz * zz), 1e-6f);
        float zux = zx / znrm, zuy = zy / znrm, zuz = zz / znrm;

        sfr[0] = xux; sfr[1] = xuy; sfr[2] = xuz;
        sfr[3] = yux; sfr[4] = yuy; sfr[5] = yuz;
        sfr[6] = zux; sfr[7] = zuy; sfr[8] = zuz;
        sorig[0] = cbx; sorig[1] = cby; sorig[2] = cbz;

        float* cbo = out + n * 12;
        cbo[0] = Nx;  cbo[1] = Ny;  cbo[2] = Nz;
        cbo[3] = Ax;  cbo[4] = Ay;  cbo[5] = Az;
        cbo[6] = Bx;  cbo[7] = By;  cbo[8] = Bz;
        cbo[9] = cbx; cbo[10] = cby; cbo[11] = cbz;
        float* fro = out + FR_OFF + n * 9;
        fro[0] = xux; fro[1] = xuy; fro[2] = xuz;
        fro[3] = yux; fro[4] = yuy; fro[5] = yuz;
        fro[6] = zux; fro[7] = zuy; fro[8] = zuz;
    }
    __syncthreads();

    const float fr0 = sfr[0], fr1 = sfr[1], fr2 = sfr[2];
    const float ox = sorig[0], oy = sorig[1], oz = sorig[2];

    // thread owns the x-line; 4 voxels per k-iter:
    //   pair A lanes = (x=k,   x=k+8)
    //   pair B lanes = (x=k+4, x=k+12), k = 0..3
    // pair-B positions derived from pair A each iteration (saves 6 u64 regs)
    const float vy = (float)(tid >> 4) - 4.0f;
    const float vz = (float)(tid & 15) - 8.0f;
    float px0 = ox + (-8.0f) * fr0 + vy * sfr[3] + vz * sfr[6];
    float py0 = oy + (-8.0f) * fr1 + vy * sfr[4] + vz * sfr[7];
    float pz0 = oz + (-8.0f) * fr2 + vy * sfr[5] + vz * sfr[8];
    u64 pxA = pk2(px0, px0 + 8.0f * fr0);
    u64 pyA = pk2(py0, py0 + 8.0f * fr1);
    u64 pzA = pk2(pz0, pz0 + 8.0f * fr2);
    const u64 sxp = pk2(fr0, fr0);
    const u64 syp = pk2(fr1, fr1);
    const u64 szp = pk2(fr2, fr2);
    const u64 four2 = pk2(4.0f, 4.0f);

    #pragma unroll 1
    for (int k = 0; k < 4; k++) {
        // pair-B positions derived on the fly
        u64 pxB = fma2_(four2, sxp, pxA);
        u64 pyB = fma2_(four2, syp, pyA);
        u64 pzB = fma2_(four2, szp, pzA);
        // |p|^2 per pair (amortized over the atom loop)
        u64 pp2A = fma2_(pxA, pxA, fma2_(pyA, pyA, mul2(pzA, pzA)));
        u64 pp2B = fma2_(pxB, pxB, fma2_(pyB, pyB, mul2(pzB, pzB)));
        u64 SA = 0ULL, TxA = 0ULL, TyA = 0ULL, TzA = 0ULL;
        u64 SB = 0ULL, TxB = 0ULL, TyB = 0ULL, TzB = 0ULL;
        // unroll 2: halves loop-control overhead vs unroll 1 while keeping the
        // live load-temp set small enough for the 64-reg occ-4 cap
        #pragma unroll 2
        for (int j = 0; j < NA; j++) {
            ulonglong2 t0 = *reinterpret_cast<const ulonglong2*>(satom + j * 8);     // -2Cx, -2Cy
            ulonglong2 t1 = *reinterpret_cast<const ulonglong2*>(satom + j * 8 + 2); // -2Cz, |C|^2
            // d2 = |p|^2 + (p.(-2C) + |C|^2)
            u64 d2A = add2(pp2A, fma2_(pxA, t0.x, fma2_(pyA, t0.y, fma2_(pzA, t1.x, t1.y))));
            u64 d2B = add2(pp2B, fma2_(pxB, t0.x, fma2_(pyB, t0.y, fma2_(pzB, t1.x, t1.y))));
            u64 rA = rfactor2(d2A);
            u64 rB = rfactor2(d2B);
            ulonglong2 t2 = *reinterpret_cast<const ulonglong2*>(satom + j * 8 + 4); // pc, -pcCx
            ulonglong2 t3 = *reinterpret_cast<const ulonglong2*>(satom + j * 8 + 6); // -pcCy, -pcCz
            SA  = fma2_(rA, t2.x, SA);
            TxA = fma2_(rA, t2.y, TxA);
            TyA = fma2_(rA, t3.x, TyA);
            TzA = fma2_(rA, t3.y, TzA);
            SB  = fma2_(rB, t2.x, SB);
            TxB = fma2_(rB, t2.y, TxB);
            TyB = fma2_(rB, t3.x, TyB);
            TzB = fma2_(rB, t3.y, TzB);
        }
        // f = S*p + T  (T accumulated with -pc*C)
        u64 fxA = fma2_(SA, pxA, TxA);
        u64 fyA = fma2_(SA, pyA, TyA);
        u64 fzA = fma2_(SA, pzA, TzA);
        u64 fxB = fma2_(SB, pxB, TxB);
        u64 fyB = fma2_(SB, pyB, TyB);
        u64 fzB = fma2_(SB, pzB, TzB);

        float v0x, v1x, v0y, v1y, v0z, v1z;
        upk2(fxA, v0x, v1x); upk2(fyA, v0y, v1y); upk2(fzA, v0z, v1z);
        {
            float fn0 = fmaxf(fmaf(v0x, v0x, fmaf(v0y, v0y, v0z * v0z)), 1e-38f);
            float fn1 = fmaxf(fmaf(v1x, v1x, fmaf(v1y, v1y, v1z * v1z)), 1e-38f);
            float r0 = rsqrt_fast(fn0), r1 = rsqrt_fast(fn1);
            int i0 = tid + (k << 8), i1 = i0 + 2048;
            sfx[i0] = v0x * r0; sfx[i1] = v1x * r1;
            sfy[i0] = v0y * r0; sfy[i1] = v1y * r1;
            sfz[i0] = v0z * r0; sfz[i1] = v1z * r1;
        }
        upk2(fxB, v0x, v1x); upk2(fyB, v0y, v1y); upk2(fzB, v0z, v1z);
        {
            float fn0 = fmaxf(fmaf(v0x, v0x, fmaf(v0y, v0y, v0z * v0z)), 1e-38f);
            float fn1 = fmaxf(fmaf(v1x, v1x, fmaf(v1y, v1y, v1z * v1z)), 1e-38f);
            float r0 = rsqrt_fast(fn0), r1 = rsqrt_fast(fn1);
            int i0 = tid + (k << 8) + 1024, i1 = i0 + 2048;
            sfx[i0] = v0x * r0; sfx[i1] = v1x * r1;
            sfy[i0] = v0y * r0; sfy[i1] = v1y * r1;
            sfz[i0] = v0z * r0; sfz[i1] = v1z * r1;
        }
        pxA = add2(pxA, sxp);
        pyA = add2(pyA, syp);
        pzA = add2(pzA, szp);
    }
    __syncthreads();

    // ---- divergence (CELL_DIM r = 1) ----
    // Branch-free clamped stencil for the lane-divergent y/z dims:
    //   dd = (f[i+p] - f[i-m]) * w  with (p,m,w) = (1,1,0.5) interior,
    //   (1,0,1) at low edge, (0,1,1) at high edge. Exactly equal to the
    //   reference's one-sided/central differences.
    float* dvo = out + DIV_OFF + n * NV;
    const int y = tid >> 4;
    const int z = tid & 15;
    const int yp = (y < 15) ? 16 : 0;
    const int ym = (y > 0)  ? 16 : 0;
    const float wy = (yp && ym) ? 0.5f : 1.0f;
    const int zp = (z < 15) ? 1 : 0;
    const int zm = (z > 0)  ? 1 : 0;
    const float wz = (zp && zm) ? 0.5f : 1.0f;
    #pragma unroll
    for (int k = 0; k < 16; k++) {
        int i = tid + (k << 8);
        float ddx;
        if (k == 0)        ddx = sfx[i + 256] - sfx[i];          // compile-time branch
        else if (k == 15)  ddx = sfx[i] - sfx[i - 256];
        else               ddx = 0.5f * (sfx[i + 256] - sfx[i - 256]);
        float ddy = (sfy[i + yp] - sfy[i - ym]) * wy;
        float ddz = (sfz[i + zp] - sfz[i - zm]) * wz;
        dvo[i] = ddx + ddy + ddz;
    }
}

extern "C" void kernel_launch(void* const* d_in, const int* in_sizes, int n_in,
                              void* d_out, int out_size) {
    const float* C         = (const float*)d_in[0];
    const int*   L         = (const int*)d_in[1];
    const float* atom_mask = (const float*)d_in[2];
    const float* charges   = (const float*)d_in[3];
    float* out = (float*)d_out;

    static bool attr_set = false;
    if (!attr_set) {
        cudaFuncSetAttribute(pp_kernel, cudaFuncAttributeMaxDynamicSharedMemorySize, 64 * 1024);
        attr_set = true;
    }
    pp_kernel<<<ZN, NTHREADS, 3 * NV * sizeof(float)>>>(C, L, atom_mask, charges, out);
}